// round 11
// baseline (speedup 1.0000x reference)
#include <cuda_runtime.h>
#include <cstdint>

#define B 16
#define S 4096
#define E 2048
#define WIN 64
#define ROWS (B * S)
#define NWIN (S - WIN + 1)     // 4033
#define CHUNKS 16
#define WPB 256                 // window starts per chunk
#define EPI_BLOCKS (B * CHUNKS) // 256

__device__ float g_scores[ROWS];
__device__ float g_part[EPI_BLOCKS];
__device__ int   g_cnt;         // zero-init; reset by last block each run

// ---------------------------------------------------------------------------
// Kernel 1: EXACT R3 dot kernel. One warp per row; MLP-batched float4 loads.
// ---------------------------------------------------------------------------
__global__ __launch_bounds__(256) void dot_kernel(
    const float* __restrict__ x,
    const int*   __restrict__ mask,   // int32 {0,1} or float32 {0.,1.} bit patterns
    const float* __restrict__ W,
    const float* __restrict__ bias)
{
    const int warp = (blockIdx.x * blockDim.x + threadIdx.x) >> 5;  // row id
    const int lane = threadIdx.x & 31;
    if (warp >= ROWS) return;

    const float4* __restrict__ xr = reinterpret_cast<const float4*>(x) + (size_t)warp * (E / 4);
    const float4* __restrict__ Wv = reinterpret_cast<const float4*>(W);

    float s0 = 0.f, s1 = 0.f, s2 = 0.f, s3 = 0.f;
    #pragma unroll
    for (int i = 0; i < 16; i += 4) {
        float4 a0 = xr[lane + (i + 0) * 32];
        float4 a1 = xr[lane + (i + 1) * 32];
        float4 a2 = xr[lane + (i + 2) * 32];
        float4 a3 = xr[lane + (i + 3) * 32];
        float4 w0 = Wv[lane + (i + 0) * 32];
        float4 w1 = Wv[lane + (i + 1) * 32];
        float4 w2 = Wv[lane + (i + 2) * 32];
        float4 w3 = Wv[lane + (i + 3) * 32];
        s0 += a0.x * w0.x + a0.y * w0.y + a0.z * w0.z + a0.w * w0.w;
        s1 += a1.x * w1.x + a1.y * w1.y + a1.z * w1.z + a1.w * w1.w;
        s2 += a2.x * w2.x + a2.y * w2.y + a2.z * w2.z + a2.w * w2.w;
        s3 += a3.x * w3.x + a3.y * w3.y + a3.z * w3.z + a3.w * w3.w;
    }
    float sum = (s0 + s1) + (s2 + s3);

    #pragma unroll
    for (int o = 16; o > 0; o >>= 1)
        sum += __shfl_xor_sync(0xFFFFFFFFu, sum, o);

    if (lane == 0) {
        float tot = sum + bias[0];
        g_scores[warp] = (mask[warp] != 0) ? tot : 0.0f;
    }
}

// ---------------------------------------------------------------------------
// Kernel 2: single-launch epilogue. grid=(CHUNKS,B), 256 threads.
// Thread t owns window start base+t: stride-1 smem (conflict-free).
// Last-finishing block does the 256-way final max + writes out[].
// ---------------------------------------------------------------------------
__global__ __launch_bounds__(256) void epilogue_kernel(float* __restrict__ out)
{
    const int chunk = blockIdx.x;
    const int b     = blockIdx.y;
    const int t     = threadIdx.x;
    const int base  = chunk * WPB;

    __shared__ float sm[WPB + WIN - 1];   // 319 floats
    const float* __restrict__ src = g_scores + (size_t)b * S;
    for (int i = t; i < WPB + WIN - 1; i += 256) {
        int idx = base + i;
        sm[i] = (idx < S) ? src[idx] : 0.0f;
    }
    __syncthreads();

    float best = -3.4e38f;
    if (base + t < NWIN) {
        float acc = 0.0f;
        #pragma unroll
        for (int k = 0; k < WIN; k++) acc += sm[t + k];
        best = acc;
    }

    #pragma unroll
    for (int o = 16; o > 0; o >>= 1)
        best = fmaxf(best, __shfl_xor_sync(0xFFFFFFFFu, best, o));

    __shared__ float pm[8];
    __shared__ int   is_last;
    if ((t & 31) == 0) pm[t >> 5] = best;
    __syncthreads();

    if (t == 0) {
        float m = pm[0];
        #pragma unroll
        for (int i = 1; i < 8; i++) m = fmaxf(m, pm[i]);
        g_part[b * CHUNKS + chunk] = m;
        __threadfence();
        int prev = atomicAdd(&g_cnt, 1);
        is_last = (prev == EPI_BLOCKS - 1) ? 1 : 0;
    }
    __syncthreads();
    if (!is_last) return;

    // ---- last block: final 256-way max -> out[B] ----
    __threadfence();
    float v = g_part[t];                       // t in [0,256): [batch][chunk]
    // reduce 16 chunks per batch: lanes t = b*16 + c
    #pragma unroll
    for (int o = 8; o > 0; o >>= 1)
        v = fmaxf(v, __shfl_xor_sync(0xFFFFFFFFu, v, o));
    // now each group of 16 lanes holds its batch max; lane with c==0 writes
    if ((t & 15) == 0)
        out[t >> 4] = v / (float)WIN;
    if (t == 0) g_cnt = 0;                     // reset for graph replay
}

extern "C" void kernel_launch(void* const* d_in, const int* in_sizes, int n_in,
                              void* d_out, int out_size)
{
    const float* x    = (const float*)d_in[0];
    const int*   mask = (const int*)  d_in[1];
    const float* W    = (const float*)d_in[2];
    const float* bias = (const float*)d_in[3];
    float*       out  = (float*)d_out;

    dot_kernel<<<ROWS / 8, 256>>>(x, mask, W, bias);   // 8 warps/block, 1 row/warp
    epilogue_kernel<<<dim3(CHUNKS, B), 256>>>(out);
}

// round 13
// speedup vs baseline: 1.0107x; 1.0107x over previous
#include <cuda_runtime.h>
#include <cstdint>

#define B 16
#define S 4096
#define E 2048
#define WIN 64
#define ROWS (B * S)
#define NWIN (S - WIN + 1)     // 4033
#define CHUNKS 16
#define WPB 256                 // window starts per chunk
#define EPI_BLOCKS (B * CHUNKS) // 256

__device__ float g_scores[ROWS];
__device__ float g_part[EPI_BLOCKS];
__device__ int   g_cnt;         // zero-init; reset by last block each run

// ---------------------------------------------------------------------------
// Kernel 1: EXACT R3 dot kernel + PDL trigger after the score store.
// ---------------------------------------------------------------------------
__global__ __launch_bounds__(256) void dot_kernel(
    const float* __restrict__ x,
    const int*   __restrict__ mask,   // int32 {0,1} or float32 {0.,1.} bit patterns
    const float* __restrict__ W,
    const float* __restrict__ bias)
{
    const int warp = (blockIdx.x * blockDim.x + threadIdx.x) >> 5;  // row id
    const int lane = threadIdx.x & 31;

    const float4* __restrict__ xr = reinterpret_cast<const float4*>(x) + (size_t)warp * (E / 4);
    const float4* __restrict__ Wv = reinterpret_cast<const float4*>(W);

    float s0 = 0.f, s1 = 0.f, s2 = 0.f, s3 = 0.f;
    #pragma unroll
    for (int i = 0; i < 16; i += 4) {
        float4 a0 = xr[lane + (i + 0) * 32];
        float4 a1 = xr[lane + (i + 1) * 32];
        float4 a2 = xr[lane + (i + 2) * 32];
        float4 a3 = xr[lane + (i + 3) * 32];
        float4 w0 = Wv[lane + (i + 0) * 32];
        float4 w1 = Wv[lane + (i + 1) * 32];
        float4 w2 = Wv[lane + (i + 2) * 32];
        float4 w3 = Wv[lane + (i + 3) * 32];
        s0 += a0.x * w0.x + a0.y * w0.y + a0.z * w0.z + a0.w * w0.w;
        s1 += a1.x * w1.x + a1.y * w1.y + a1.z * w1.z + a1.w * w1.w;
        s2 += a2.x * w2.x + a2.y * w2.y + a2.z * w2.z + a2.w * w2.w;
        s3 += a3.x * w3.x + a3.y * w3.y + a3.z * w3.z + a3.w * w3.w;
    }
    float sum = (s0 + s1) + (s2 + s3);

    #pragma unroll
    for (int o = 16; o > 0; o >>= 1)
        sum += __shfl_xor_sync(0xFFFFFFFFu, sum, o);

    if (lane == 0) {
        float tot = sum + bias[0];
        g_scores[warp] = (mask[warp] != 0) ? tot : 0.0f;
    }

    // Allow the PDL-dependent epilogue grid to begin dispatching.
    cudaTriggerProgrammaticLaunchCompletion();
}

// ---------------------------------------------------------------------------
// Kernel 2: epilogue, launched with Programmatic Stream Serialization.
// Blocks get placed during dot's tail wave and park in the HW-backed
// grid-dependency wait; zero L2 poll traffic during the streaming phase.
// ---------------------------------------------------------------------------
__global__ __launch_bounds__(256) void epilogue_kernel(float* __restrict__ out)
{
    // Wait for dot_kernel completion + memory flush (HW dependency, not a spin).
    cudaGridDependencySynchronize();

    const int chunk = blockIdx.x;
    const int b     = blockIdx.y;
    const int t     = threadIdx.x;
    const int base  = chunk * WPB;

    __shared__ float sm[WPB + WIN - 1];   // 319 floats
    const float* __restrict__ src = g_scores + (size_t)b * S;
    for (int i = t; i < WPB + WIN - 1; i += 256) {
        int idx = base + i;
        sm[i] = (idx < S) ? src[idx] : 0.0f;
    }
    __syncthreads();

    float best = -3.4e38f;
    if (base + t < NWIN) {
        float acc = 0.0f;
        #pragma unroll
        for (int k = 0; k < WIN; k++) acc += sm[t + k];
        best = acc;
    }

    #pragma unroll
    for (int o = 16; o > 0; o >>= 1)
        best = fmaxf(best, __shfl_xor_sync(0xFFFFFFFFu, best, o));

    __shared__ float pm[8];
    __shared__ int   is_last;
    if ((t & 31) == 0) pm[t >> 5] = best;
    __syncthreads();

    if (t == 0) {
        float m = pm[0];
        #pragma unroll
        for (int i = 1; i < 8; i++) m = fmaxf(m, pm[i]);
        g_part[b * CHUNKS + chunk] = m;
        __threadfence();
        int prev = atomicAdd(&g_cnt, 1);
        is_last = (prev == EPI_BLOCKS - 1) ? 1 : 0;
    }
    __syncthreads();
    if (!is_last) return;

    // ---- last block: final 256-way max -> out[B] ----
    __threadfence();
    float v = g_part[t];                       // t = b*16 + c
    #pragma unroll
    for (int o = 8; o > 0; o >>= 1)
        v = fmaxf(v, __shfl_xor_sync(0xFFFFFFFFu, v, o));
    if ((t & 15) == 0)
        out[t >> 4] = v / (float)WIN;
    if (t == 0) g_cnt = 0;                     // reset for graph replay
}

extern "C" void kernel_launch(void* const* d_in, const int* in_sizes, int n_in,
                              void* d_out, int out_size)
{
    const float* x    = (const float*)d_in[0];
    const int*   mask = (const int*)  d_in[1];
    const float* W    = (const float*)d_in[2];
    const float* bias = (const float*)d_in[3];
    float*       out  = (float*)d_out;

    dot_kernel<<<ROWS / 8, 256>>>(x, mask, W, bias);   // 8 warps/block, 1 row/warp

    // Epilogue with Programmatic Stream Serialization (PDL).
    cudaLaunchConfig_t cfg = {};
    cfg.gridDim  = dim3(CHUNKS, B);
    cfg.blockDim = dim3(256);
    cfg.dynamicSmemBytes = 0;
    cfg.stream = 0;
    cudaLaunchAttribute attr[1];
    attr[0].id = cudaLaunchAttributeProgrammaticStreamSerialization;
    attr[0].val.programmaticStreamSerializationAllowed = 1;
    cfg.attrs = attr;
    cfg.numAttrs = 1;
    cudaLaunchKernelEx(&cfg, epilogue_kernel, out);
}